// round 11
// baseline (speedup 1.0000x reference)
#include <cuda_runtime.h>
#include <cstdint>
#include <math.h>

#define BN 4096
#define DD 256
#define EE 131072
#define NE (EE + BN)
#define NP 8128
#define NPAD 8192
#define NEG 0.2f
#define EPSG 1e-10f
#define MAXDEG 1024

typedef unsigned long long ull;

// ---------------- device scratch (no allocations allowed) ----------------
__device__ float g_h[BN * DD];
__device__ float g_x1[BN * DD];
__device__ float g_x2[BN * DD];
__device__ float g_as[BN];
__device__ float g_ad[BN];
__device__ int   g_cnt[BN];
__device__ int   g_start[BN + 1];
__device__ int   g_pos[BN];
__device__ int   g_srcs[NE];
__device__ float g_wd[DD * NPAD];   // fc weight diff [d][p], zero-padded to 8192 cols
__device__ float g_bd[NP];
__device__ unsigned char g_adj[(size_t)BN * NP];

// ---------------- edge counting sort (done once, reused for all layers) ----------------
__global__ void k_zero_cnt() {
    int i = blockIdx.x * blockDim.x + threadIdx.x;
    if (i < BN) g_cnt[i] = 0;
}

__global__ void k_hist(const int* __restrict__ ei) {
    int i = blockIdx.x * blockDim.x + threadIdx.x;
    if (i < NE) {
        int dst = (i < EE) ? ei[EE + i] : (i - EE);
        atomicAdd(&g_cnt[dst], 1);
    }
}

__global__ void k_scan() {  // 1 block, 1024 threads, 4 elems each
    __shared__ int sh[1024];
    int tid = threadIdx.x;
    int b = tid * 4;
    int v0 = g_cnt[b], v1 = g_cnt[b + 1], v2 = g_cnt[b + 2], v3 = g_cnt[b + 3];
    int ls = v0 + v1 + v2 + v3;
    sh[tid] = ls;
    __syncthreads();
    for (int off = 1; off < 1024; off <<= 1) {
        int t = (tid >= off) ? sh[tid - off] : 0;
        __syncthreads();
        sh[tid] += t;
        __syncthreads();
    }
    int run = sh[tid] - ls;  // exclusive prefix
    g_start[b] = run;     g_pos[b] = run;     run += v0;
    g_start[b + 1] = run; g_pos[b + 1] = run; run += v1;
    g_start[b + 2] = run; g_pos[b + 2] = run; run += v2;
    g_start[b + 3] = run; g_pos[b + 3] = run; run += v3;
    if (tid == 1023) g_start[BN] = run;
}

__global__ void k_scatter(const int* __restrict__ ei) {
    int i = blockIdx.x * blockDim.x + threadIdx.x;
    if (i < NE) {
        int src = (i < EE) ? ei[i] : (i - EE);
        int dst = (i < EE) ? ei[EE + i] : (i - EE);
        int p = atomicAdd(&g_pos[dst], 1);
        g_srcs[p] = src;
    }
}

// ---------------- fc weight diff precompute ----------------
__global__ void k_wdiff(const float* __restrict__ fcW, const float* __restrict__ fcb) {
    int p = blockIdx.x * blockDim.x + threadIdx.x;  // 0..8191
    int d = blockIdx.y;                              // 0..255
    float v = 0.0f;
    if (p < NP) {
        v = fcW[d * (2 * NP) + 2 * p] - fcW[d * (2 * NP) + 2 * p + 1];
        if (d == 0) g_bd[p] = fcb[2 * p] - fcb[2 * p + 1];
    }
    g_wd[d * NPAD + p] = v;
}

// ---------------- h = x @ W  (4096x256x256), 64x64 tile ----------------
__global__ void __launch_bounds__(256) k_gemm_h(const float* __restrict__ xext, int insel,
                                                const float* __restrict__ W) {
    const float* X = (insel == 0) ? xext : ((insel == 1) ? g_x1 : g_x2);
    __shared__ float As[16][68];
    __shared__ float Bs[16][64];
    int tid = threadIdx.x;
    int tx = tid % 16, ty = tid / 16;
    int m0 = blockIdx.y * 64, n0 = blockIdx.x * 64;

    int am = tid / 4, ak = (tid % 4) * 4;     // A: 64 rows x 16 k
    int bk = tid / 16, bn = (tid % 16) * 4;   // B: 16 k x 64 cols

    float acc[4][4];
#pragma unroll
    for (int i = 0; i < 4; i++)
#pragma unroll
        for (int j = 0; j < 4; j++) acc[i][j] = 0.0f;

    const float* Ap = X + (m0 + am) * DD + ak;
    const float* Bp = W + bk * DD + n0 + bn;

    float4 av = *(const float4*)Ap;
    float4 bv = *(const float4*)Bp;

    for (int kb = 0; kb < DD; kb += 16) {
        __syncthreads();
        As[ak + 0][am] = av.x; As[ak + 1][am] = av.y;
        As[ak + 2][am] = av.z; As[ak + 3][am] = av.w;
        *(float4*)&Bs[bk][bn] = bv;
        __syncthreads();
        if (kb + 16 < DD) {
            av = *(const float4*)(Ap + kb + 16);
            bv = *(const float4*)(Bp + (kb + 16) * DD);
        }
#pragma unroll
        for (int kk = 0; kk < 16; kk++) {
            float4 a = *(float4*)&As[kk][ty * 4];
            float4 b = *(float4*)&Bs[kk][tx * 4];
            float ar[4] = {a.x, a.y, a.z, a.w};
            float br[4] = {b.x, b.y, b.z, b.w};
#pragma unroll
            for (int i = 0; i < 4; i++)
#pragma unroll
                for (int j = 0; j < 4; j++) acc[i][j] = fmaf(ar[i], br[j], acc[i][j]);
        }
    }
#pragma unroll
    for (int i = 0; i < 4; i++) {
        float4 r = make_float4(acc[i][0], acc[i][1], acc[i][2], acc[i][3]);
        *(float4*)&g_h[(m0 + ty * 4 + i) * DD + n0 + tx * 4] = r;
    }
}

// ---------------- attention coefficients ----------------
__global__ void k_attn(const float* __restrict__ asrc, const float* __restrict__ adst) {
    int warp = threadIdx.x / 32, lane = threadIdx.x % 32;
    int r = blockIdx.x * 8 + warp;
    float s = 0.0f, d = 0.0f;
#pragma unroll
    for (int k = 0; k < 8; k++) {
        int c = lane + 32 * k;
        float v = g_h[r * DD + c];
        s = fmaf(v, asrc[c], s);
        d = fmaf(v, adst[c], d);
    }
#pragma unroll
    for (int o = 16; o; o >>= 1) {
        s += __shfl_xor_sync(0xffffffffu, s, o);
        d += __shfl_xor_sync(0xffffffffu, d, o);
    }
    if (lane == 0) { g_as[r] = s; g_ad[r] = d; }
}

// ---------------- per-node segment softmax + weighted aggregation (atomic-free) ----------------
__global__ void __launch_bounds__(256) k_agg(const float* __restrict__ gatb, int outsel) {
    __shared__ float se[MAXDEG];
    __shared__ int   ss[MAXDEG];
    __shared__ float red[32];
    int n = blockIdx.x, tid = threadIdx.x;
    int s0 = g_start[n];
    int deg = g_start[n + 1] - s0;
    if (deg > MAXDEG) deg = MAXDEG;
    float adn = g_ad[n];
    for (int t = tid; t < deg; t += 256) {
        int s = g_srcs[s0 + t];
        ss[t] = s;
        float e = g_as[s] + adn;
        se[t] = (e >= 0.0f) ? e : NEG * e;
    }
    __syncthreads();
    float m = -3.4e38f;
    for (int t = tid; t < deg; t += 256) m = fmaxf(m, se[t]);
#pragma unroll
    for (int o = 16; o; o >>= 1) m = fmaxf(m, __shfl_xor_sync(0xffffffffu, m, o));
    if ((tid & 31) == 0) red[tid >> 5] = m;
    __syncthreads();
    if (tid < 32) {
        float v = (tid < 8) ? red[tid] : -3.4e38f;
#pragma unroll
        for (int o = 4; o; o >>= 1) v = fmaxf(v, __shfl_xor_sync(0xffffffffu, v, o));
        if (tid == 0) red[0] = v;
    }
    __syncthreads();
    m = red[0];
    __syncthreads();
    float s = 0.0f;
    for (int t = tid; t < deg; t += 256) {
        float ex = expf(se[t] - m);
        se[t] = ex;
        s += ex;
    }
#pragma unroll
    for (int o = 16; o; o >>= 1) s += __shfl_xor_sync(0xffffffffu, s, o);
    if ((tid & 31) == 0) red[tid >> 5] = s;
    __syncthreads();
    if (tid < 32) {
        float v = (tid < 8) ? red[tid] : 0.0f;
#pragma unroll
        for (int o = 4; o; o >>= 1) v += __shfl_xor_sync(0xffffffffu, v, o);
        if (tid == 0) red[0] = v;
    }
    __syncthreads();
    float denom = red[0];
    __syncthreads();
    for (int t = tid; t < deg; t += 256) se[t] = se[t] / denom;
    __syncthreads();
    float acc = 0.0f;
    int t = 0;
    for (; t + 4 <= deg; t += 4) {
        float a0 = se[t], a1 = se[t + 1], a2 = se[t + 2], a3 = se[t + 3];
        float v0 = g_h[ss[t] * DD + tid];
        float v1 = g_h[ss[t + 1] * DD + tid];
        float v2 = g_h[ss[t + 2] * DD + tid];
        float v3 = g_h[ss[t + 3] * DD + tid];
        acc = fmaf(a0, v0, acc);
        acc = fmaf(a1, v1, acc);
        acc = fmaf(a2, v2, acc);
        acc = fmaf(a3, v3, acc);
    }
    for (; t < deg; t++) acc = fmaf(se[t], g_h[ss[t] * DD + tid], acc);
    float* xo = (outsel == 1) ? g_x1 : g_x2;
    xo[n * DD + tid] = acc + gatb[tid];
}

// ---------------- FC diff-GEMM (4096 x 8192pad x 256): scalar FFMA, K-chunk 16 ------------
// 128x128 tile, 8x8 per thread (contiguous rows ty*8.., cols tx*8..).
// K staged 16 at a time (half the __syncthreads of the K=8 version); same FMA order per
// output accumulator -> margins bitwise identical to R10.
// Epilogue: sign(t + g0 - g1) == sign(e^t * L1 - L0), MUFU fast math (proven zero-flip).
__global__ void __launch_bounds__(256) k_fc(const float* __restrict__ gum) {
    __shared__ float As[16][132];   // As[k][m] (A transposed)
    __shared__ float Bs[16][128];   // Bs[k][n]
    int tid = threadIdx.x;
    int tx = tid % 16, ty = tid / 16;          // cols tx*8..+7, rows ty*8..+7
    int m0 = blockIdx.y * 128, n0 = blockIdx.x * 128;

    int arow = tid / 2, ak8 = (tid % 2) * 8;   // A producer: 128 rows x 16 k (2 float4/thread)
    int bk = tid / 16, bc = (tid % 16) * 8;    // B producer: 16 k x 128 cols (2 float4/thread)

    float acc[8][8];
#pragma unroll
    for (int i = 0; i < 8; i++)
#pragma unroll
        for (int j = 0; j < 8; j++) acc[i][j] = 0.0f;

    const float* Ap = g_x1 + (size_t)(m0 + arow) * DD + ak8;
    const float* Bp = g_wd + (size_t)bk * NPAD + n0 + bc;

    float4 av0 = *(const float4*)Ap;
    float4 av1 = *(const float4*)(Ap + 4);
    float4 bv0 = *(const float4*)Bp;
    float4 bv1 = *(const float4*)(Bp + 4);

    for (int kb = 0; kb < DD; kb += 16) {
        __syncthreads();
        As[ak8 + 0][arow] = av0.x; As[ak8 + 1][arow] = av0.y;
        As[ak8 + 2][arow] = av0.z; As[ak8 + 3][arow] = av0.w;
        As[ak8 + 4][arow] = av1.x; As[ak8 + 5][arow] = av1.y;
        As[ak8 + 6][arow] = av1.z; As[ak8 + 7][arow] = av1.w;
        *(float4*)&Bs[bk][bc] = bv0;
        *(float4*)&Bs[bk][bc + 4] = bv1;
        __syncthreads();
        if (kb + 16 < DD) {
            av0 = *(const float4*)(Ap + kb + 16);
            av1 = *(const float4*)(Ap + kb + 20);
            bv0 = *(const float4*)(Bp + (size_t)(kb + 16) * NPAD);
            bv1 = *(const float4*)(Bp + (size_t)(kb + 16) * NPAD + 4);
        }
#pragma unroll
        for (int kk = 0; kk < 16; kk++) {
            float4 a0 = *(float4*)&As[kk][ty * 8];
            float4 a1 = *(float4*)&As[kk][ty * 8 + 4];
            float4 b0 = *(float4*)&Bs[kk][tx * 8];
            float4 b1 = *(float4*)&Bs[kk][tx * 8 + 4];
            float ar[8] = {a0.x, a0.y, a0.z, a0.w, a1.x, a1.y, a1.z, a1.w};
            float br[8] = {b0.x, b0.y, b0.z, b0.w, b1.x, b1.y, b1.z, b1.w};
#pragma unroll
            for (int i = 0; i < 8; i++)
#pragma unroll
                for (int j = 0; j < 8; j++) acc[i][j] = fmaf(ar[i], br[j], acc[i][j]);
        }
    }

    // ---- epilogue: bias + gumbel sign -> adjacency bytes (MUFU fast math, validated) ----
    int p0 = n0 + tx * 8;
    if (p0 >= NP) return;  // 8128 boundary is 8-aligned
    float bdv[8];
    *(float4*)&bdv[0] = *(const float4*)&g_bd[p0];
    *(float4*)&bdv[4] = *(const float4*)&g_bd[p0 + 4];

#pragma unroll
    for (int i = 0; i < 8; i++) {
        int r = m0 + ty * 8 + i;
        const float* gp = gum + ((size_t)r * NP + p0) * 2;
        float4 ua = *(const float4*)(gp + 0);
        float4 ub = *(const float4*)(gp + 4);
        float4 uc = *(const float4*)(gp + 8);
        float4 ud = *(const float4*)(gp + 12);
        float u0[8] = {ua.x, ua.z, ub.x, ub.z, uc.x, uc.z, ud.x, ud.z};
        float u1[8] = {ua.y, ua.w, ub.y, ub.w, uc.y, uc.w, ud.y, ud.w};
        ull bits = 0ull;
#pragma unroll
        for (int j = 0; j < 8; j++) {
            float t = acc[i][j] + bdv[j];
            float L0 = EPSG - __logf(u0[j] + EPSG);
            float L1 = EPSG - __logf(u1[j] + EPSG);
            // t + g0 - g1 >= 0  <=>  exp(t)*L1 >= L0   (L1 > 0)
            if (__expf(t) * L1 - L0 >= 0.0f) bits |= (1ull << (8 * j));
        }
        *(ull*)(g_adj + (size_t)r * NP + p0) = bits;
    }
}

// ---------------- expand adjacency bits to symmetric 128x128 float matrices ----------------
// thread -> (row i = tid/2, col-half = tid%2); triangular index maintained incrementally:
//   j > i: p = C + j (C precomputed);  j < i: p += (126 - j) per step.  Bytes identical.
__global__ void __launch_bounds__(256) k_expand(float* __restrict__ out) {
    __shared__ int4 sbuf[NP / 16];  // 8128 bytes
    unsigned char* sa = (unsigned char*)sbuf;
    int n = blockIdx.x, tid = threadIdx.x;
    const int4* srcp = (const int4*)(g_adj + (size_t)n * NP);
    for (int t = tid; t < NP / 16; t += 256) sbuf[t] = srcp[t];
    __syncthreads();
    int i = tid >> 1;
    int j0 = (tid & 1) << 6;          // 0 or 64
    float* orow = out + (size_t)n * 16384 + (i << 7) + j0;
    int C = i * 127 - (i * (i - 1)) / 2 - i - 1;              // p = C + j   for j > i
    int p_lt = j0 * 127 - (j0 * (j0 - 1)) / 2 + i - j0 - 1;   // running p   for j < i
#pragma unroll 4
    for (int jb = 0; jb < 64; jb += 4) {
        float v[4];
#pragma unroll
        for (int q = 0; q < 4; q++) {
            int j = j0 + jb + q;
            int p = (j < i) ? p_lt : (C + j);
            float r = (i == j) ? 0.0f : (float)sa[p];
            v[q] = r;
            if (j < i) p_lt += 126 - j;
        }
        *(float4*)&orow[jb] = make_float4(v[0], v[1], v[2], v[3]);
    }
}

extern "C" void kernel_launch(void* const* d_in, const int* in_sizes, int n_in,
                              void* d_out, int out_size) {
    const float* x    = (const float*)d_in[0];
    const int*   ei   = (const int*)d_in[1];
    const float* gum  = (const float*)d_in[2];
    const float* gatW = (const float*)d_in[3];
    const float* asrc = (const float*)d_in[4];
    const float* adst = (const float*)d_in[5];
    const float* gatb = (const float*)d_in[6];
    const float* fcW  = (const float*)d_in[7];
    const float* fcb  = (const float*)d_in[8];
    float* out = (float*)d_out;

    (void)in_sizes; (void)n_in; (void)out_size;

    // edge counting sort (reused by all 3 layers)
    k_zero_cnt<<<(BN + 255) / 256, 256>>>();
    k_hist<<<(NE + 255) / 256, 256>>>(ei);
    k_scan<<<1, 1024>>>();

    // layer-1 gemm early (profile slot); scatter must only precede k_agg.
    k_gemm_h<<<dim3(DD / 64, BN / 64), 256>>>(x, 0, gatW);
    k_scatter<<<(NE + 255) / 256, 256>>>(ei);
    k_wdiff<<<dim3(NPAD / 256, DD), 256>>>(fcW, fcb);
    k_attn<<<BN / 8, 256>>>(asrc, adst);
    k_agg<<<BN, 256>>>(gatb, 1);

    // layers 2, 3; ping-pong: x1 -> x2 -> x1
    for (int l = 1; l < 3; l++) {
        int insel = (l == 1) ? 1 : 2;
        int outsel = (l == 1) ? 2 : 1;
        k_gemm_h<<<dim3(DD / 64, BN / 64), 256>>>(x, insel, gatW + (size_t)l * DD * DD);
        k_attn<<<BN / 8, 256>>>(asrc + l * DD, adst + l * DD);
        k_agg<<<BN, 256>>>(gatb + l * DD, outsel);
    }

    // FC diff-GEMM (scalar FFMA, K-chunk 16) + fast gumbel sign -> adjacency bits
    k_fc<<<dim3(NPAD / 128, BN / 128), 256>>>(gum);

    // expand to symmetric output
    k_expand<<<BN, 256>>>(out);
}

// round 12
// speedup vs baseline: 1.1023x; 1.1023x over previous
#include <cuda_runtime.h>
#include <cstdint>
#include <math.h>

#define BN 4096
#define DD 256
#define EE 131072
#define NE (EE + BN)
#define NP 8128
#define NPAD 8192
#define NEG 0.2f
#define EPSG 1e-10f
#define MAXDEG 1024

typedef unsigned long long ull;

// ---------------- device scratch (no allocations allowed) ----------------
__device__ float g_h[BN * DD];
__device__ float g_x1[BN * DD];
__device__ float g_x2[BN * DD];
__device__ float g_as[BN];
__device__ float g_ad[BN];
__device__ int   g_cnt[BN];
__device__ int   g_start[BN + 1];
__device__ int   g_pos[BN];
__device__ int   g_srcs[NE];
__device__ float g_wd[DD * NPAD];   // fc weight diff [d][p], zero-padded to 8192 cols
__device__ float g_bd[NP];
__device__ unsigned char g_adj[(size_t)BN * NP];

// ---------------- edge counting sort (done once, reused for all layers) ----------------
__global__ void k_zero_cnt() {
    int i = blockIdx.x * blockDim.x + threadIdx.x;
    if (i < BN) g_cnt[i] = 0;
}

__global__ void k_hist(const int* __restrict__ ei) {
    int i = blockIdx.x * blockDim.x + threadIdx.x;
    if (i < NE) {
        int dst = (i < EE) ? ei[EE + i] : (i - EE);
        atomicAdd(&g_cnt[dst], 1);
    }
}

__global__ void k_scan() {  // 1 block, 1024 threads, 4 elems each
    __shared__ int sh[1024];
    int tid = threadIdx.x;
    int b = tid * 4;
    int v0 = g_cnt[b], v1 = g_cnt[b + 1], v2 = g_cnt[b + 2], v3 = g_cnt[b + 3];
    int ls = v0 + v1 + v2 + v3;
    sh[tid] = ls;
    __syncthreads();
    for (int off = 1; off < 1024; off <<= 1) {
        int t = (tid >= off) ? sh[tid - off] : 0;
        __syncthreads();
        sh[tid] += t;
        __syncthreads();
    }
    int run = sh[tid] - ls;  // exclusive prefix
    g_start[b] = run;     g_pos[b] = run;     run += v0;
    g_start[b + 1] = run; g_pos[b + 1] = run; run += v1;
    g_start[b + 2] = run; g_pos[b + 2] = run; run += v2;
    g_start[b + 3] = run; g_pos[b + 3] = run; run += v3;
    if (tid == 1023) g_start[BN] = run;
}

__global__ void k_scatter(const int* __restrict__ ei) {
    int i = blockIdx.x * blockDim.x + threadIdx.x;
    if (i < NE) {
        int src = (i < EE) ? ei[i] : (i - EE);
        int dst = (i < EE) ? ei[EE + i] : (i - EE);
        int p = atomicAdd(&g_pos[dst], 1);
        g_srcs[p] = src;
    }
}

// ---------------- fc weight diff precompute ----------------
__global__ void k_wdiff(const float* __restrict__ fcW, const float* __restrict__ fcb) {
    int p = blockIdx.x * blockDim.x + threadIdx.x;  // 0..8191
    int d = blockIdx.y;                              // 0..255
    float v = 0.0f;
    if (p < NP) {
        v = fcW[d * (2 * NP) + 2 * p] - fcW[d * (2 * NP) + 2 * p + 1];
        if (d == 0) g_bd[p] = fcb[2 * p] - fcb[2 * p + 1];
    }
    g_wd[d * NPAD + p] = v;
}

// ---------------- h = x @ W  (4096x256x256), 32x64 tile (512 CTAs, latency-friendly) ------
// Per-output FMA chain is strictly ascending k -> h bitwise identical to the 64x64 version.
__global__ void __launch_bounds__(256) k_gemm_h(const float* __restrict__ xext, int insel,
                                                const float* __restrict__ W) {
    const float* X = (insel == 0) ? xext : ((insel == 1) ? g_x1 : g_x2);
    __shared__ float As[16][34];
    __shared__ float Bs[16][64];
    int tid = threadIdx.x;
    int tx = tid % 16, ty = tid / 16;         // cols n0+tx*4.., rows m0+ty*2..
    int m0 = blockIdx.y * 32, n0 = blockIdx.x * 64;

    int am = tid / 8, ak = (tid % 8) * 2;     // A: 32 rows x 16 k, float2 per thread
    int bk = tid / 16, bn = (tid % 16) * 4;   // B: 16 k x 64 cols, float4 per thread

    float acc[2][4];
#pragma unroll
    for (int i = 0; i < 2; i++)
#pragma unroll
        for (int j = 0; j < 4; j++) acc[i][j] = 0.0f;

    const float* Ap = X + (m0 + am) * DD + ak;
    const float* Bp = W + bk * DD + n0 + bn;

    float2 av = *(const float2*)Ap;
    float4 bv = *(const float4*)Bp;

    for (int kb = 0; kb < DD; kb += 16) {
        __syncthreads();
        As[ak + 0][am] = av.x;
        As[ak + 1][am] = av.y;
        *(float4*)&Bs[bk][bn] = bv;
        __syncthreads();
        if (kb + 16 < DD) {
            av = *(const float2*)(Ap + kb + 16);
            bv = *(const float4*)(Bp + (kb + 16) * DD);
        }
#pragma unroll
        for (int kk = 0; kk < 16; kk++) {
            float a0 = As[kk][ty * 2];
            float a1 = As[kk][ty * 2 + 1];
            float4 b = *(float4*)&Bs[kk][tx * 4];
            float br[4] = {b.x, b.y, b.z, b.w};
#pragma unroll
            for (int j = 0; j < 4; j++) {
                acc[0][j] = fmaf(a0, br[j], acc[0][j]);
                acc[1][j] = fmaf(a1, br[j], acc[1][j]);
            }
        }
    }
#pragma unroll
    for (int i = 0; i < 2; i++) {
        float4 r = make_float4(acc[i][0], acc[i][1], acc[i][2], acc[i][3]);
        *(float4*)&g_h[(size_t)(m0 + ty * 2 + i) * DD + n0 + tx * 4] = r;
    }
}

// ---------------- attention coefficients ----------------
__global__ void k_attn(const float* __restrict__ asrc, const float* __restrict__ adst) {
    int warp = threadIdx.x / 32, lane = threadIdx.x % 32;
    int r = blockIdx.x * 8 + warp;
    float s = 0.0f, d = 0.0f;
#pragma unroll
    for (int k = 0; k < 8; k++) {
        int c = lane + 32 * k;
        float v = g_h[r * DD + c];
        s = fmaf(v, asrc[c], s);
        d = fmaf(v, adst[c], d);
    }
#pragma unroll
    for (int o = 16; o; o >>= 1) {
        s += __shfl_xor_sync(0xffffffffu, s, o);
        d += __shfl_xor_sync(0xffffffffu, d, o);
    }
    if (lane == 0) { g_as[r] = s; g_ad[r] = d; }
}

// ---------------- per-node segment softmax + weighted aggregation (atomic-free) ----------------
__global__ void __launch_bounds__(256) k_agg(const float* __restrict__ gatb, int outsel) {
    __shared__ float se[MAXDEG];
    __shared__ int   ss[MAXDEG];
    __shared__ float red[32];
    int n = blockIdx.x, tid = threadIdx.x;
    int s0 = g_start[n];
    int deg = g_start[n + 1] - s0;
    if (deg > MAXDEG) deg = MAXDEG;
    float adn = g_ad[n];
    for (int t = tid; t < deg; t += 256) {
        int s = g_srcs[s0 + t];
        ss[t] = s;
        float e = g_as[s] + adn;
        se[t] = (e >= 0.0f) ? e : NEG * e;
    }
    __syncthreads();
    float m = -3.4e38f;
    for (int t = tid; t < deg; t += 256) m = fmaxf(m, se[t]);
#pragma unroll
    for (int o = 16; o; o >>= 1) m = fmaxf(m, __shfl_xor_sync(0xffffffffu, m, o));
    if ((tid & 31) == 0) red[tid >> 5] = m;
    __syncthreads();
    if (tid < 32) {
        float v = (tid < 8) ? red[tid] : -3.4e38f;
#pragma unroll
        for (int o = 4; o; o >>= 1) v = fmaxf(v, __shfl_xor_sync(0xffffffffu, v, o));
        if (tid == 0) red[0] = v;
    }
    __syncthreads();
    m = red[0];
    __syncthreads();
    float s = 0.0f;
    for (int t = tid; t < deg; t += 256) {
        float ex = expf(se[t] - m);
        se[t] = ex;
        s += ex;
    }
#pragma unroll
    for (int o = 16; o; o >>= 1) s += __shfl_xor_sync(0xffffffffu, s, o);
    if ((tid & 31) == 0) red[tid >> 5] = s;
    __syncthreads();
    if (tid < 32) {
        float v = (tid < 8) ? red[tid] : 0.0f;
#pragma unroll
        for (int o = 4; o; o >>= 1) v += __shfl_xor_sync(0xffffffffu, v, o);
        if (tid == 0) red[0] = v;
    }
    __syncthreads();
    float denom = red[0];
    __syncthreads();
    for (int t = tid; t < deg; t += 256) se[t] = se[t] / denom;
    __syncthreads();
    float acc = 0.0f;
    int t = 0;
    for (; t + 4 <= deg; t += 4) {
        float a0 = se[t], a1 = se[t + 1], a2 = se[t + 2], a3 = se[t + 3];
        float v0 = g_h[ss[t] * DD + tid];
        float v1 = g_h[ss[t + 1] * DD + tid];
        float v2 = g_h[ss[t + 2] * DD + tid];
        float v3 = g_h[ss[t + 3] * DD + tid];
        acc = fmaf(a0, v0, acc);
        acc = fmaf(a1, v1, acc);
        acc = fmaf(a2, v2, acc);
        acc = fmaf(a3, v3, acc);
    }
    for (; t < deg; t++) acc = fmaf(se[t], g_h[ss[t] * DD + tid], acc);
    float* xo = (outsel == 1) ? g_x1 : g_x2;
    xo[n * DD + tid] = acc + gatb[tid];
}

// ---------------- FC diff-GEMM (4096 x 8192pad x 256): scalar FFMA (R10 form, PROVEN) -----
// 128x128 tile, 8x8 per thread, K-chunk 8. DO NOT PERTURB (R11's K=16 regressed -86us).
// Epilogue: sign(t + g0 - g1) == sign(e^t * L1 - L0), MUFU fast math (proven zero-flip).
__global__ void __launch_bounds__(256) k_fc(const float* __restrict__ gum) {
    __shared__ float As[8][132];   // As[k][m] (A transposed)
    __shared__ float Bs[8][128];   // Bs[k][n]
    int tid = threadIdx.x;
    int tx = tid % 16, ty = tid / 16;          // cols tx*8..+7, rows ty*8..+7
    int m0 = blockIdx.y * 128, n0 = blockIdx.x * 128;

    int arow = tid / 2, ak = (tid % 2) * 4;    // A producer: 128 rows x 8 k
    int bk = tid / 32, bc = (tid % 32) * 4;    // B producer: 8 k x 128 cols

    float acc[8][8];
#pragma unroll
    for (int i = 0; i < 8; i++)
#pragma unroll
        for (int j = 0; j < 8; j++) acc[i][j] = 0.0f;

    const float* Ap = g_x1 + (size_t)(m0 + arow) * DD + ak;
    const float* Bp = g_wd + (size_t)bk * NPAD + n0 + bc;

    float4 av = *(const float4*)Ap;
    float4 bv = *(const float4*)Bp;

    for (int kb = 0; kb < DD; kb += 8) {
        __syncthreads();
        As[ak + 0][arow] = av.x; As[ak + 1][arow] = av.y;
        As[ak + 2][arow] = av.z; As[ak + 3][arow] = av.w;
        *(float4*)&Bs[bk][bc] = bv;
        __syncthreads();
        if (kb + 8 < DD) {
            av = *(const float4*)(Ap + kb + 8);
            bv = *(const float4*)(Bp + (size_t)(kb + 8) * NPAD);
        }
#pragma unroll
        for (int kk = 0; kk < 8; kk++) {
            float4 a0 = *(float4*)&As[kk][ty * 8];
            float4 a1 = *(float4*)&As[kk][ty * 8 + 4];
            float4 b0 = *(float4*)&Bs[kk][tx * 8];
            float4 b1 = *(float4*)&Bs[kk][tx * 8 + 4];
            float ar[8] = {a0.x, a0.y, a0.z, a0.w, a1.x, a1.y, a1.z, a1.w};
            float br[8] = {b0.x, b0.y, b0.z, b0.w, b1.x, b1.y, b1.z, b1.w};
#pragma unroll
            for (int i = 0; i < 8; i++)
#pragma unroll
                for (int j = 0; j < 8; j++) acc[i][j] = fmaf(ar[i], br[j], acc[i][j]);
        }
    }

    // ---- epilogue: bias + gumbel sign -> adjacency bytes (MUFU fast math, validated) ----
    int p0 = n0 + tx * 8;
    if (p0 >= NP) return;  // 8128 boundary is 8-aligned
    float bdv[8];
    *(float4*)&bdv[0] = *(const float4*)&g_bd[p0];
    *(float4*)&bdv[4] = *(const float4*)&g_bd[p0 + 4];

#pragma unroll
    for (int i = 0; i < 8; i++) {
        int r = m0 + ty * 8 + i;
        const float* gp = gum + ((size_t)r * NP + p0) * 2;
        float4 ua = *(const float4*)(gp + 0);
        float4 ub = *(const float4*)(gp + 4);
        float4 uc = *(const float4*)(gp + 8);
        float4 ud = *(const float4*)(gp + 12);
        float u0[8] = {ua.x, ua.z, ub.x, ub.z, uc.x, uc.z, ud.x, ud.z};
        float u1[8] = {ua.y, ua.w, ub.y, ub.w, uc.y, uc.w, ud.y, ud.w};
        ull bits = 0ull;
#pragma unroll
        for (int j = 0; j < 8; j++) {
            float t = acc[i][j] + bdv[j];
            float L0 = EPSG - __logf(u0[j] + EPSG);
            float L1 = EPSG - __logf(u1[j] + EPSG);
            // t + g0 - g1 >= 0  <=>  exp(t)*L1 >= L0   (L1 > 0)
            if (__expf(t) * L1 - L0 >= 0.0f) bits |= (1ull << (8 * j));
        }
        *(ull*)(g_adj + (size_t)r * NP + p0) = bits;
    }
}

// ---------------- expand adjacency bits to symmetric 128x128 float matrices (R10 form) ----
__global__ void __launch_bounds__(256) k_expand(float* __restrict__ out) {
    __shared__ int4 sbuf[NP / 16];  // 8128 bytes
    unsigned char* sa = (unsigned char*)sbuf;
    int n = blockIdx.x, tid = threadIdx.x;
    const int4* srcp = (const int4*)(g_adj + (size_t)n * NP);
    for (int t = tid; t < NP / 16; t += 256) sbuf[t] = srcp[t];
    __syncthreads();
    float* o = out + (size_t)n * 16384;
    for (int idx = tid; idx < 4096; idx += 256) {
        int i = idx >> 5;
        int j0 = (idx & 31) << 2;
        float v[4];
#pragma unroll
        for (int q = 0; q < 4; q++) {
            int j = j0 + q;
            float r = 0.0f;
            if (i != j) {
                int a = (i < j) ? i : j;
                int b = (i < j) ? j : i;
                int p = a * 127 - (a * (a - 1)) / 2 + (b - a - 1);
                r = (float)sa[p];
            }
            v[q] = r;
        }
        *(float4*)&o[(i << 7) + j0] = make_float4(v[0], v[1], v[2], v[3]);
    }
}

extern "C" void kernel_launch(void* const* d_in, const int* in_sizes, int n_in,
                              void* d_out, int out_size) {
    const float* x    = (const float*)d_in[0];
    const int*   ei   = (const int*)d_in[1];
    const float* gum  = (const float*)d_in[2];
    const float* gatW = (const float*)d_in[3];
    const float* asrc = (const float*)d_in[4];
    const float* adst = (const float*)d_in[5];
    const float* gatb = (const float*)d_in[6];
    const float* fcW  = (const float*)d_in[7];
    const float* fcb  = (const float*)d_in[8];
    float* out = (float*)d_out;

    (void)in_sizes; (void)n_in; (void)out_size;

    // edge counting sort (reused by all 3 layers)
    k_zero_cnt<<<(BN + 255) / 256, 256>>>();
    k_hist<<<(NE + 255) / 256, 256>>>(ei);
    k_scan<<<1, 1024>>>();

    // layer-1 gemm early (profile slot); scatter must only precede k_agg.
    k_gemm_h<<<dim3(DD / 64, BN / 32), 256>>>(x, 0, gatW);
    k_scatter<<<(NE + 255) / 256, 256>>>(ei);
    k_wdiff<<<dim3(NPAD / 256, DD), 256>>>(fcW, fcb);
    k_attn<<<BN / 8, 256>>>(asrc, adst);
    k_agg<<<BN, 256>>>(gatb, 1);

    // layers 2, 3; ping-pong: x1 -> x2 -> x1
    for (int l = 1; l < 3; l++) {
        int insel = (l == 1) ? 1 : 2;
        int outsel = (l == 1) ? 2 : 1;
        k_gemm_h<<<dim3(DD / 64, BN / 32), 256>>>(x, insel, gatW + (size_t)l * DD * DD);
        k_attn<<<BN / 8, 256>>>(asrc + l * DD, adst + l * DD);
        k_agg<<<BN, 256>>>(gatb + l * DD, outsel);
    }

    // FC diff-GEMM (scalar FFMA, K-chunk 8 — R10 proven) + fast gumbel sign
    k_fc<<<dim3(NPAD / 128, BN / 128), 256>>>(gum);

    // expand to symmetric output
    k_expand<<<BN, 256>>>(out);
}

// round 17
// speedup vs baseline: 1.1373x; 1.0317x over previous
#include <cuda_runtime.h>
#include <cstdint>
#include <math.h>

#define BN 4096
#define DD 256
#define EE 131072
#define NE (EE + BN)
#define NP 8128
#define NPAD 8192
#define NEG 0.2f
#define EPSG 1e-10f
#define MAXDEG 1024

typedef unsigned long long ull;

// ---------------- device scratch (no allocations allowed) ----------------
__device__ float g_h[BN * DD];
__device__ float g_hp[BN * DD];     // split-K partial (k >= 128)
__device__ float g_x1[BN * DD];
__device__ float g_x2[BN * DD];
__device__ float g_as[BN];
__device__ float g_ad[BN];
__device__ int   g_cnt[BN];
__device__ int   g_start[BN + 1];
__device__ int   g_pos[BN];
__device__ int   g_srcs[NE];
__device__ float g_wd[DD * NPAD];   // fc weight diff [d][p], zero-padded to 8192 cols
__device__ float g_bd[NP];
__device__ unsigned char g_adj[(size_t)BN * NP];

// ---------------- edge counting sort (done once, reused for all layers) ----------------
__global__ void k_zero_cnt() {
    int i = blockIdx.x * blockDim.x + threadIdx.x;
    if (i < BN) g_cnt[i] = 0;
}

__global__ void k_hist(const int* __restrict__ ei) {
    int i = blockIdx.x * blockDim.x + threadIdx.x;
    if (i < NE) {
        int dst = (i < EE) ? ei[EE + i] : (i - EE);
        atomicAdd(&g_cnt[dst], 1);
    }
}

__global__ void k_scan() {  // 1 block, 1024 threads, 4 elems each
    __shared__ int sh[1024];
    int tid = threadIdx.x;
    int b = tid * 4;
    int v0 = g_cnt[b], v1 = g_cnt[b + 1], v2 = g_cnt[b + 2], v3 = g_cnt[b + 3];
    int ls = v0 + v1 + v2 + v3;
    sh[tid] = ls;
    __syncthreads();
    for (int off = 1; off < 1024; off <<= 1) {
        int t = (tid >= off) ? sh[tid - off] : 0;
        __syncthreads();
        sh[tid] += t;
        __syncthreads();
    }
    int run = sh[tid] - ls;  // exclusive prefix
    g_start[b] = run;     g_pos[b] = run;     run += v0;
    g_start[b + 1] = run; g_pos[b + 1] = run; run += v1;
    g_start[b + 2] = run; g_pos[b + 2] = run; run += v2;
    g_start[b + 3] = run; g_pos[b + 3] = run; run += v3;
    if (tid == 1023) g_start[BN] = run;
}

__global__ void k_scatter(const int* __restrict__ ei) {
    int i = blockIdx.x * blockDim.x + threadIdx.x;
    if (i < NE) {
        int src = (i < EE) ? ei[i] : (i - EE);
        int dst = (i < EE) ? ei[EE + i] : (i - EE);
        int p = atomicAdd(&g_pos[dst], 1);
        g_srcs[p] = src;
    }
}

// ---------------- fc weight diff precompute ----------------
__global__ void k_wdiff(const float* __restrict__ fcW, const float* __restrict__ fcb) {
    int p = blockIdx.x * blockDim.x + threadIdx.x;  // 0..8191
    int d = blockIdx.y;                              // 0..255
    float v = 0.0f;
    if (p < NP) {
        v = fcW[d * (2 * NP) + 2 * p] - fcW[d * (2 * NP) + 2 * p + 1];
        if (d == 0) g_bd[p] = fcb[2 * p] - fcb[2 * p + 1];
    }
    g_wd[d * NPAD + p] = v;
}

// ---------------- h = x @ W, split-K: 64x64 tile, z in {0,1} covers k half ----------------
// Same 4x4/thread intensity as the proven R10 tile; grid 512 for latency hiding.
__global__ void __launch_bounds__(256) k_gemm_h(const float* __restrict__ xext, int insel,
                                                const float* __restrict__ W) {
    const float* X = (insel == 0) ? xext : ((insel == 1) ? g_x1 : g_x2);
    __shared__ float As[16][68];
    __shared__ float Bs[16][64];
    int tid = threadIdx.x;
    int tx = tid % 16, ty = tid / 16;
    int m0 = blockIdx.y * 64, n0 = blockIdx.x * 64;
    int kz = blockIdx.z * 128;
    float* H = (blockIdx.z == 0) ? g_h : g_hp;

    int am = tid / 4, ak = (tid % 4) * 4;     // A: 64 rows x 16 k
    int bk = tid / 16, bn = (tid % 16) * 4;   // B: 16 k x 64 cols

    float acc[4][4];
#pragma unroll
    for (int i = 0; i < 4; i++)
#pragma unroll
        for (int j = 0; j < 4; j++) acc[i][j] = 0.0f;

    const float* Ap = X + (size_t)(m0 + am) * DD + kz + ak;
    const float* Bp = W + (size_t)(kz + bk) * DD + n0 + bn;

    float4 av = *(const float4*)Ap;
    float4 bv = *(const float4*)Bp;

    for (int kb = 0; kb < 128; kb += 16) {
        __syncthreads();
        As[ak + 0][am] = av.x; As[ak + 1][am] = av.y;
        As[ak + 2][am] = av.z; As[ak + 3][am] = av.w;
        *(float4*)&Bs[bk][bn] = bv;
        __syncthreads();
        if (kb + 16 < 128) {
            av = *(const float4*)(Ap + kb + 16);
            bv = *(const float4*)(Bp + (size_t)(kb + 16) * DD);
        }
#pragma unroll
        for (int kk = 0; kk < 16; kk++) {
            float4 a = *(float4*)&As[kk][ty * 4];
            float4 b = *(float4*)&Bs[kk][tx * 4];
            float ar[4] = {a.x, a.y, a.z, a.w};
            float br[4] = {b.x, b.y, b.z, b.w};
#pragma unroll
            for (int i = 0; i < 4; i++)
#pragma unroll
                for (int j = 0; j < 4; j++) acc[i][j] = fmaf(ar[i], br[j], acc[i][j]);
        }
    }
#pragma unroll
    for (int i = 0; i < 4; i++) {
        float4 r = make_float4(acc[i][0], acc[i][1], acc[i][2], acc[i][3]);
        *(float4*)&H[(size_t)(m0 + ty * 4 + i) * DD + n0 + tx * 4] = r;
    }
}

// ---------------- combine split-K halves + attention coefficients (fused) ----------------
// h = h_lo + h_hi written back to g_h; dot products in the same pass.
__global__ void k_haddattn(const float* __restrict__ asrc, const float* __restrict__ adst) {
    int warp = threadIdx.x / 32, lane = threadIdx.x % 32;
    int r = blockIdx.x * 8 + warp;
    float s = 0.0f, d = 0.0f;
#pragma unroll
    for (int k = 0; k < 8; k++) {
        int c = lane + 32 * k;
        size_t idx = (size_t)r * DD + c;
        float v = g_h[idx] + g_hp[idx];
        g_h[idx] = v;
        s = fmaf(v, asrc[c], s);
        d = fmaf(v, adst[c], d);
    }
#pragma unroll
    for (int o = 16; o; o >>= 1) {
        s += __shfl_xor_sync(0xffffffffu, s, o);
        d += __shfl_xor_sync(0xffffffffu, d, o);
    }
    if (lane == 0) { g_as[r] = s; g_ad[r] = d; }
}

// ---------------- per-node segment softmax + weighted aggregation (atomic-free) ----------------
__global__ void __launch_bounds__(256) k_agg(const float* __restrict__ gatb, int outsel) {
    __shared__ float se[MAXDEG];
    __shared__ int   ss[MAXDEG];
    __shared__ float red[32];
    int n = blockIdx.x, tid = threadIdx.x;
    int s0 = g_start[n];
    int deg = g_start[n + 1] - s0;
    if (deg > MAXDEG) deg = MAXDEG;
    float adn = g_ad[n];
    for (int t = tid; t < deg; t += 256) {
        int s = g_srcs[s0 + t];
        ss[t] = s;
        float e = g_as[s] + adn;
        se[t] = (e >= 0.0f) ? e : NEG * e;
    }
    __syncthreads();
    float m = -3.4e38f;
    for (int t = tid; t < deg; t += 256) m = fmaxf(m, se[t]);
#pragma unroll
    for (int o = 16; o; o >>= 1) m = fmaxf(m, __shfl_xor_sync(0xffffffffu, m, o));
    if ((tid & 31) == 0) red[tid >> 5] = m;
    __syncthreads();
    if (tid < 32) {
        float v = (tid < 8) ? red[tid] : -3.4e38f;
#pragma unroll
        for (int o = 4; o; o >>= 1) v = fmaxf(v, __shfl_xor_sync(0xffffffffu, v, o));
        if (tid == 0) red[0] = v;
    }
    __syncthreads();
    m = red[0];
    __syncthreads();
    float s = 0.0f;
    for (int t = tid; t < deg; t += 256) {
        float ex = expf(se[t] - m);
        se[t] = ex;
        s += ex;
    }
#pragma unroll
    for (int o = 16; o; o >>= 1) s += __shfl_xor_sync(0xffffffffu, s, o);
    if ((tid & 31) == 0) red[tid >> 5] = s;
    __syncthreads();
    if (tid < 32) {
        float v = (tid < 8) ? red[tid] : 0.0f;
#pragma unroll
        for (int o = 4; o; o >>= 1) v += __shfl_xor_sync(0xffffffffu, v, o);
        if (tid == 0) red[0] = v;
    }
    __syncthreads();
    float denom = red[0];
    __syncthreads();
    for (int t = tid; t < deg; t += 256) se[t] = se[t] / denom;
    __syncthreads();
    float acc = 0.0f;
    int t = 0;
    for (; t + 4 <= deg; t += 4) {
        float a0 = se[t], a1 = se[t + 1], a2 = se[t + 2], a3 = se[t + 3];
        float v0 = g_h[ss[t] * DD + tid];
        float v1 = g_h[ss[t + 1] * DD + tid];
        float v2 = g_h[ss[t + 2] * DD + tid];
        float v3 = g_h[ss[t + 3] * DD + tid];
        acc = fmaf(a0, v0, acc);
        acc = fmaf(a1, v1, acc);
        acc = fmaf(a2, v2, acc);
        acc = fmaf(a3, v3, acc);
    }
    for (; t < deg; t++) acc = fmaf(se[t], g_h[ss[t] * DD + tid], acc);
    float* xo = (outsel == 1) ? g_x1 : g_x2;
    xo[n * DD + tid] = acc + gatb[tid];
}

// ---------------- FC diff-GEMM (4096 x 8192pad x 256): scalar FFMA (R10 form, PROVEN) -----
// 128x128 tile, 8x8 per thread, K-chunk 8. DO NOT PERTURB (R11's K=16 regressed -86us).
// Epilogue: sign(t + g0 - g1) == sign(e^t * L1 - L0), MUFU fast math (proven zero-flip).
__global__ void __launch_bounds__(256) k_fc(const float* __restrict__ gum) {
    __shared__ float As[8][132];   // As[k][m] (A transposed)
    __shared__ float Bs[8][128];   // Bs[k][n]
    int tid = threadIdx.x;
    int tx = tid % 16, ty = tid / 16;          // cols tx*8..+7, rows ty*8..+7
    int m0 = blockIdx.y * 128, n0 = blockIdx.x * 128;

    int arow = tid / 2, ak = (tid % 2) * 4;    // A producer: 128 rows x 8 k
    int bk = tid / 32, bc = (tid % 32) * 4;    // B producer: 8 k x 128 cols

    float acc[8][8];
#pragma unroll
    for (int i = 0; i < 8; i++)
#pragma unroll
        for (int j = 0; j < 8; j++) acc[i][j] = 0.0f;

    const float* Ap = g_x1 + (size_t)(m0 + arow) * DD + ak;
    const float* Bp = g_wd + (size_t)bk * NPAD + n0 + bc;

    float4 av = *(const float4*)Ap;
    float4 bv = *(const float4*)Bp;

    for (int kb = 0; kb < DD; kb += 8) {
        __syncthreads();
        As[ak + 0][arow] = av.x; As[ak + 1][arow] = av.y;
        As[ak + 2][arow] = av.z; As[ak + 3][arow] = av.w;
        *(float4*)&Bs[bk][bc] = bv;
        __syncthreads();
        if (kb + 8 < DD) {
            av = *(const float4*)(Ap + kb + 8);
            bv = *(const float4*)(Bp + (size_t)(kb + 8) * NPAD);
        }
#pragma unroll
        for (int kk = 0; kk < 8; kk++) {
            float4 a0 = *(float4*)&As[kk][ty * 8];
            float4 a1 = *(float4*)&As[kk][ty * 8 + 4];
            float4 b0 = *(float4*)&Bs[kk][tx * 8];
            float4 b1 = *(float4*)&Bs[kk][tx * 8 + 4];
            float ar[8] = {a0.x, a0.y, a0.z, a0.w, a1.x, a1.y, a1.z, a1.w};
            float br[8] = {b0.x, b0.y, b0.z, b0.w, b1.x, b1.y, b1.z, b1.w};
#pragma unroll
            for (int i = 0; i < 8; i++)
#pragma unroll
                for (int j = 0; j < 8; j++) acc[i][j] = fmaf(ar[i], br[j], acc[i][j]);
        }
    }

    // ---- epilogue: bias + gumbel sign -> adjacency bytes (MUFU fast math, validated) ----
    int p0 = n0 + tx * 8;
    if (p0 >= NP) return;  // 8128 boundary is 8-aligned
    float bdv[8];
    *(float4*)&bdv[0] = *(const float4*)&g_bd[p0];
    *(float4*)&bdv[4] = *(const float4*)&g_bd[p0 + 4];

#pragma unroll
    for (int i = 0; i < 8; i++) {
        int r = m0 + ty * 8 + i;
        const float* gp = gum + ((size_t)r * NP + p0) * 2;
        float4 ua = *(const float4*)(gp + 0);
        float4 ub = *(const float4*)(gp + 4);
        float4 uc = *(const float4*)(gp + 8);
        float4 ud = *(const float4*)(gp + 12);
        float u0[8] = {ua.x, ua.z, ub.x, ub.z, uc.x, uc.z, ud.x, ud.z};
        float u1[8] = {ua.y, ua.w, ub.y, ub.w, uc.y, uc.w, ud.y, ud.w};
        ull bits = 0ull;
#pragma unroll
        for (int j = 0; j < 8; j++) {
            float t = acc[i][j] + bdv[j];
            float L0 = EPSG - __logf(u0[j] + EPSG);
            float L1 = EPSG - __logf(u1[j] + EPSG);
            // t + g0 - g1 >= 0  <=>  exp(t)*L1 >= L0   (L1 > 0)
            if (__expf(t) * L1 - L0 >= 0.0f) bits |= (1ull << (8 * j));
        }
        *(ull*)(g_adj + (size_t)r * NP + p0) = bits;
    }
}

// ---------------- expand adjacency bits to symmetric 128x128 float matrices (R10 form) ----
__global__ void __launch_bounds__(256) k_expand(float* __restrict__ out) {
    __shared__ int4 sbuf[NP / 16];  // 8128 bytes
    unsigned char* sa = (unsigned char*)sbuf;
    int n = blockIdx.x, tid = threadIdx.x;
    const int4* srcp = (const int4*)(g_adj + (size_t)n * NP);
    for (int t = tid; t < NP / 16; t += 256) sbuf[t] = srcp[t];
    __syncthreads();
    float* o = out + (size_t)n * 16384;
    for (int idx = tid; idx < 4096; idx += 256) {
        int i = idx >> 5;
        int j0 = (idx & 31) << 2;
        float v[4];
#pragma unroll
        for (int q = 0; q < 4; q++) {
            int j = j0 + q;
            float r = 0.0f;
            if (i != j) {
                int a = (i < j) ? i : j;
                int b = (i < j) ? j : i;
                int p = a * 127 - (a * (a - 1)) / 2 + (b - a - 1);
                r = (float)sa[p];
            }
            v[q] = r;
        }
        *(float4*)&o[(i << 7) + j0] = make_float4(v[0], v[1], v[2], v[3]);
    }
}

extern "C" void kernel_launch(void* const* d_in, const int* in_sizes, int n_in,
                              void* d_out, int out_size) {
    const float* x    = (const float*)d_in[0];
    const int*   ei   = (const int*)d_in[1];
    const float* gum  = (const float*)d_in[2];
    const float* gatW = (const float*)d_in[3];
    const float* asrc = (const float*)d_in[4];
    const float* adst = (const float*)d_in[5];
    const float* gatb = (const float*)d_in[6];
    const float* fcW  = (const float*)d_in[7];
    const float* fcb  = (const float*)d_in[8];
    float* out = (float*)d_out;

    (void)in_sizes; (void)n_in; (void)out_size;

    dim3 ggrid(DD / 64, BN / 64, 2);   // split-K: z = k-half

    // edge counting sort (reused by all 3 layers)
    k_zero_cnt<<<(BN + 255) / 256, 256>>>();
    k_hist<<<(NE + 255) / 256, 256>>>(ei);
    k_scan<<<1, 1024>>>();

    // layer-1 gemm early (profile slot); scatter must only precede k_agg.
    k_gemm_h<<<ggrid, 256>>>(x, 0, gatW);
    k_scatter<<<(NE + 255) / 256, 256>>>(ei);
    k_wdiff<<<dim3(NPAD / 256, DD), 256>>>(fcW, fcb);
    k_haddattn<<<BN / 8, 256>>>(asrc, adst);
    k_agg<<<BN, 256>>>(gatb, 1);

    // layers 2, 3; ping-pong: x1 -> x2 -> x1
    for (int l = 1; l < 3; l++) {
        int insel = (l == 1) ? 1 : 2;
        int outsel = (l == 1) ? 2 : 1;
        k_gemm_h<<<ggrid, 256>>>(x, insel, gatW + (size_t)l * DD * DD);
        k_haddattn<<<BN / 8, 256>>>(asrc + l * DD, adst + l * DD);
        k_agg<<<BN, 256>>>(gatb + l * DD, outsel);
    }

    // FC diff-GEMM (scalar FFMA, K-chunk 8 — R10 proven) + fast gumbel sign
    k_fc<<<dim3(NPAD / 128, BN / 128), 256>>>(gum);

    // expand to symmetric output
    k_expand<<<BN, 256>>>(out);
}